// round 14
// baseline (speedup 1.0000x reference)
#include <cuda_runtime.h>
#include <cuda_bf16.h>
#include <math.h>
#include <stdint.h>

#define S 64
#define B 64
#define T 48
#define V 32000
#define NEG (-100000000.0f)

__device__ float g_ctxp[S * B * 512];
__device__ float g_xall[T * B * 512];
__device__ float g_gi0[T * B * 1536];
__device__ float g_Wcombo[1536 * 512];
__device__ float g_Wct[512 * 512];
__device__ float g_WdecT[512 * 512];
__device__ __nv_bfloat16 g_Wvb[(size_t)V * 512];
__device__ float g_hall[(T + 1) * B * 512];
__device__ float g_h1[B * 512];
__device__ float g_z[B * 512];
__device__ float g_gh[B * 1536];
__device__ float g_gi1[B * 1536];
__device__ float g_gh1[B * 1536];
__device__ float g_q[B * 512];
__device__ float g_lgall[T * B * 512];
__device__ __nv_bfloat16 g_logit_bf[T * B * 512];
__device__ float g_pmax[T * 250 * B];
__device__ float g_psum[T * 250 * B];
__device__ float g_tgt[T * B];
__device__ float g_losst[T];
__device__ int g_bar_count = 0;
__device__ volatile int g_bar_sense = 0;

__device__ __forceinline__ float tanh_fast(float x) {
    float y;
    asm("tanh.approx.f32 %0, %1;" : "=f"(y) : "f"(x));
    return y;
}

__device__ __forceinline__ uint32_t f2tf(float x) {
    uint32_t r;
    asm("cvt.rna.tf32.f32 %0, %1;" : "=r"(r) : "f"(x));
    return r;
}

__device__ __forceinline__ void mma_tf32(float* c, uint32_t a0, uint32_t a1,
                                         uint32_t a2, uint32_t a3,
                                         uint32_t b0, uint32_t b1) {
    asm volatile(
        "mma.sync.aligned.m16n8k8.row.col.f32.tf32.tf32.f32 "
        "{%0,%1,%2,%3}, {%4,%5,%6,%7}, {%8,%9}, {%0,%1,%2,%3};\n"
        : "+f"(c[0]), "+f"(c[1]), "+f"(c[2]), "+f"(c[3])
        : "r"(a0), "r"(a1), "r"(a2), "r"(a3), "r"(b0), "r"(b1));
}

// ---------------------------------------------------------------------------
// tf32 mma tile: C[64 x 64 tile] = A[64+ x 512] @ W[N x 512]^T, full K=512.
// ---------------------------------------------------------------------------
__device__ __forceinline__ void tile_tf32(const float* __restrict__ A,
                                          const float* __restrict__ W,
                                          float* __restrict__ C,
                                          int N, int n0, int m0,
                                          uint32_t (*As)[20], uint32_t (*Ws)[20]) {
    const int tid = threadIdx.x;
    const int warp = tid >> 5, lane = tid & 31;
    const int wm = (warp & 3) * 16, wn = (warp >> 2) * 32;
    const int g = lane >> 2, tk = lane & 3;
    const int lr = tid >> 2, lc = (tid & 3) * 4;

    const float* Ap = A + (size_t)(m0 + lr) * 512 + lc;
    const float* Wp = W + (size_t)(n0 + lr) * 512 + lc;
    float4 ra = *(const float4*)Ap;
    float4 rw = *(const float4*)Wp;

    float acc[4][4];
#pragma unroll
    for (int f = 0; f < 4; f++)
#pragma unroll
        for (int j = 0; j < 4; j++) acc[f][j] = 0.f;

    for (int kc = 0; kc < 512; kc += 16) {
        As[lr][lc + 0] = f2tf(ra.x); As[lr][lc + 1] = f2tf(ra.y);
        As[lr][lc + 2] = f2tf(ra.z); As[lr][lc + 3] = f2tf(ra.w);
        Ws[lr][lc + 0] = f2tf(rw.x); Ws[lr][lc + 1] = f2tf(rw.y);
        Ws[lr][lc + 2] = f2tf(rw.z); Ws[lr][lc + 3] = f2tf(rw.w);
        __syncthreads();
        if (kc + 16 < 512) {
            ra = *(const float4*)(Ap + kc + 16);
            rw = *(const float4*)(Wp + kc + 16);
        }
#pragma unroll
        for (int ks = 0; ks < 16; ks += 8) {
            uint32_t a0 = As[wm + g][ks + tk];
            uint32_t a1 = As[wm + g + 8][ks + tk];
            uint32_t a2 = As[wm + g][ks + tk + 4];
            uint32_t a3 = As[wm + g + 8][ks + tk + 4];
#pragma unroll
            for (int f = 0; f < 4; f++) {
                uint32_t b0 = Ws[wn + f * 8 + g][ks + tk];
                uint32_t b1 = Ws[wn + f * 8 + g][ks + tk + 4];
                mma_tf32(acc[f], a0, a1, a2, a3, b0, b1);
            }
        }
        __syncthreads();
    }
    const int r0 = m0 + wm + g, r1 = r0 + 8;
#pragma unroll
    for (int f = 0; f < 4; f++) {
        int c = n0 + wn + f * 8 + tk * 2;
        C[(size_t)r0 * N + c]     = acc[f][0];
        C[(size_t)r0 * N + c + 1] = acc[f][1];
        C[(size_t)r1 * N + c]     = acc[f][2];
        C[(size_t)r1 * N + c + 1] = acc[f][3];
    }
}

__global__ void __launch_bounds__(256, 2)
gemm_tf32(const float* __restrict__ A, const float* __restrict__ W,
          float* __restrict__ C, int N) {
    __shared__ uint32_t As[64][20];
    __shared__ uint32_t Ws[64][20];
    tile_tf32(A, W, C, N, blockIdx.x * 64, blockIdx.y * 64, As, Ws);
}

// ---------------- persistent-loop grid barrier (sense-reversing) -----------
__device__ __forceinline__ void grid_bar(int nb, int& sense) {
    sense ^= 1;
    __threadfence();
    __syncthreads();
    if (threadIdx.x == 0) {
        int v = atomicAdd(&g_bar_count, 1);
        if (v == nb - 1) {
            atomicExch(&g_bar_count, 0);
            __threadfence();
            g_bar_sense = sense;
        } else {
            while (g_bar_sense != sense) { }
            __threadfence();
        }
    }
    __syncthreads();
}

// ---------------- entire 48-step recurrence in ONE kernel ------------------
__global__ void __launch_bounds__(256, 1)
decoder_loop(const float* __restrict__ ctx, const float* __restrict__ mask,
             const float* __restrict__ w_mlp,
             const float* __restrict__ W_hh0, const float* __restrict__ W_hid2ctx,
             const float* __restrict__ W_hh1,
             const float* __restrict__ b_ih0, const float* __restrict__ b_hh0,
             const float* __restrict__ b_ih1, const float* __restrict__ b_hh1) {
    __shared__ uint32_t As[64][20];
    __shared__ uint32_t Ws[64][20];
    __shared__ float qs[512];
    __shared__ float sc[64];
    const int nb = gridDim.x, bid = blockIdx.x, tid = threadIdx.x;
    int sense = 0;

    for (int t = 0; t < T; t++) {
        const float* ht = g_hall + (size_t)t * B * 512;
        float* ht1 = g_hall + (size_t)(t + 1) * B * 512;

        // A: gh0 = h_t @ W_hh0^T   (24 n-tiles)
        for (int nt = bid; nt < 24; nt += nb)
            tile_tf32(ht, W_hh0, g_gh, 1536, nt * 64, 0, As, Ws);
        grid_bar(nb, sense);

        // B: GRU layer 0 -> g_h1
        {
            const float* gi = g_gi0 + (size_t)t * 64 * 1536;
            for (int i = bid * 256 + tid; i < 64 * 512; i += nb * 256) {
                int b = i >> 9, h = i & 511;
                size_t base = (size_t)b * 1536 + h;
                float ir = gi[base] + b_ih0[h];
                float iz = gi[base + 512] + b_ih0[512 + h];
                float in_ = gi[base + 1024] + b_ih0[1024 + h];
                float hr = g_gh[base] + b_hh0[h];
                float hz = g_gh[base + 512] + b_hh0[512 + h];
                float hn = g_gh[base + 1024] + b_hh0[1024 + h];
                float r = 1.f / (1.f + expf(-(ir + hr)));
                float zg = 1.f / (1.f + expf(-(iz + hz)));
                float n = tanhf(in_ + r * hn);
                g_h1[i] = (1.f - zg) * n + zg * ht[i];
            }
        }
        grid_bar(nb, sense);

        // C: q = h1 @ W_hid2ctx^T  (8 n-tiles)
        for (int nt = bid; nt < 8; nt += nb)
            tile_tf32(g_h1, W_hid2ctx, g_q, 512, nt * 64, 0, As, Ws);
        grid_bar(nb, sense);

        // D: attention per b
        for (int b = bid; b < 64; b += nb) {
            for (int i = tid; i < 512; i += 256) qs[i] = g_q[b * 512 + i];
            __syncthreads();
            int warp = tid >> 5, lane = tid & 31;
            for (int s = warp; s < 64; s += 8) {
                float acc = 0.f;
                const float* cp = &g_ctxp[((size_t)s * 64 + b) * 512];
                for (int c = lane; c < 512; c += 32)
                    acc += tanh_fast(cp[c] + qs[c]) * w_mlp[c];
#pragma unroll
                for (int o = 16; o > 0; o >>= 1) acc += __shfl_xor_sync(0xffffffffu, acc, o);
                if (lane == 0) sc[s] = (mask[s * 64 + b] > 0.f) ? acc : NEG;
            }
            __syncthreads();
            if (warp == 0) {
                float v0 = sc[lane], v1 = sc[lane + 32];
                float mx = fmaxf(v0, v1);
#pragma unroll
                for (int o = 16; o > 0; o >>= 1)
                    mx = fmaxf(mx, __shfl_xor_sync(0xffffffffu, mx, o));
                float e0 = expf(v0 - mx), e1 = expf(v1 - mx);
                float sm = e0 + e1;
#pragma unroll
                for (int o = 16; o > 0; o >>= 1) sm += __shfl_xor_sync(0xffffffffu, sm, o);
                sc[lane] = e0 / sm;
                sc[lane + 32] = e1 / sm;
            }
            __syncthreads();
            for (int c = tid; c < 512; c += 256) {
                float acc = 0.f;
                for (int s = 0; s < 64; s++)
                    acc += sc[s] * ctx[((size_t)s * 64 + b) * 512 + c];
                g_z[b * 512 + c] = acc;
            }
            __syncthreads();
        }
        grid_bar(nb, sense);

        // E: gi1 = z @ Wcombo^T ; gh1 = h1 @ W_hh1^T  (48 tiles)
        for (int task = bid; task < 48; task += nb) {
            if (task < 24)
                tile_tf32(g_z, g_Wcombo, g_gi1, 1536, task * 64, 0, As, Ws);
            else
                tile_tf32(g_h1, W_hh1, g_gh1, 1536, (task - 24) * 64, 0, As, Ws);
        }
        grid_bar(nb, sense);

        // F: GRU layer 1 -> h_{t+1}
        for (int i = bid * 256 + tid; i < 64 * 512; i += nb * 256) {
            int b = i >> 9, h = i & 511;
            size_t base = (size_t)b * 1536 + h;
            float ir = g_gi1[base] + b_ih1[h];
            float iz = g_gi1[base + 512] + b_ih1[512 + h];
            float in_ = g_gi1[base + 1024] + b_ih1[1024 + h];
            float hr = g_gh1[base] + b_hh1[h];
            float hz = g_gh1[base + 512] + b_hh1[512 + h];
            float hn = g_gh1[base + 1024] + b_hh1[1024 + h];
            float r = 1.f / (1.f + expf(-(ir + hr)));
            float zg = 1.f / (1.f + expf(-(iz + hz)));
            float n = tanhf(in_ + r * hn);
            ht1[i] = (1.f - zg) * n + zg * g_h1[i];
        }
        grid_bar(nb, sense);
    }
}

// ---------------- prologue / epilogue ---------------------------------------
__global__ void transpose_k(const float* __restrict__ in, float* __restrict__ out,
                            int R, int Cc) {
    __shared__ float tile[32][33];
    int bx = blockIdx.x * 32, by = blockIdx.y * 32;
    int x = bx + threadIdx.x;
#pragma unroll
    for (int i = 0; i < 32; i += 8)
        tile[threadIdx.y + i][threadIdx.x] = in[(size_t)(by + threadIdx.y + i) * Cc + x];
    __syncthreads();
    int x2 = by + threadIdx.x;
#pragma unroll
    for (int i = 0; i < 32; i += 8)
        out[(size_t)(bx + threadIdx.y + i) * R + x2] = tile[threadIdx.x][threadIdx.y + i];
}

__global__ void convert_bf16(const float* __restrict__ w) {
    size_t i = ((size_t)blockIdx.x * blockDim.x + threadIdx.x) * 4;
#pragma unroll
    for (int j = 0; j < 4; j++) g_Wvb[i + j] = __float2bfloat16(w[i + j]);
}

__global__ void gather_kernel(const int* __restrict__ y, const float* __restrict__ emb) {
    int blk = blockIdx.x;
    int t = blk >> 6, b = blk & 63;
    int id = y[t * 64 + b];
    g_xall[(size_t)blk * 512 + threadIdx.x] = emb[(size_t)id * 512 + threadIdx.x];
}

__global__ void init_kernel(const float* __restrict__ ctx, const float* __restrict__ mask,
                            const float* __restrict__ txt) {
    int b = blockIdx.x, tid = threadIdx.x;
    __shared__ float mixed[512];
    __shared__ float denom;
    float msum[2];
#pragma unroll
    for (int j = 0; j < 2; j++) {
        int c = tid + 256 * j;
        float m = 0.f;
        for (int s = 0; s < S; s++) m += ctx[((size_t)s * 64 + b) * 512 + c];
        msum[j] = m;
    }
    if (tid == 0) {
        float d = 0.f;
        for (int s = 0; s < S; s++) d += mask[s * 64 + b];
        denom = d;
    }
    __syncthreads();
#pragma unroll
    for (int j = 0; j < 2; j++) {
        int c = tid + 256 * j;
        mixed[c] = 0.5f * (msum[j] / denom) + 0.5f * txt[b * 512 + c];
    }
    __syncthreads();
    for (int h = tid; h < 512; h += 256) {
        float a = 0.f;
        for (int c = 0; c < 512; c++) a += mixed[c] * g_WdecT[c * 512 + h];
        g_hall[b * 512 + h] = tanhf(a);
    }
}

__global__ void logit_combine_all(const float* __restrict__ bias) {
    int row = blockIdx.x, e = threadIdx.x;
    float v = g_lgall[(size_t)row * 512 + e];
    g_logit_bf[(size_t)row * 512 + e] = __float2bfloat16(tanhf(v + bias[e]));
}

__device__ __forceinline__ void mma_bf16(float& c0, float& c1, float& c2, float& c3,
                                         uint32_t a0, uint32_t a1, uint32_t a2, uint32_t a3,
                                         uint32_t b0, uint32_t b1) {
    asm volatile(
        "mma.sync.aligned.m16n8k16.row.col.f32.bf16.bf16.f32 "
        "{%0,%1,%2,%3}, {%4,%5,%6,%7}, {%8,%9}, {%0,%1,%2,%3};\n"
        : "+f"(c0), "+f"(c1), "+f"(c2), "+f"(c3)
        : "r"(a0), "r"(a1), "r"(a2), "r"(a3), "r"(b0), "r"(b1));
}

__device__ __forceinline__ void cp16(uint32_t dst, const void* src) {
    asm volatile("cp.async.cg.shared.global [%0], [%1], 16;\n" :: "r"(dst), "l"(src));
}

#define SA 528
#define SBW 40
#define BCHUNK (128 * SBW * 2)
#define VOCAB_SMEM (64 * SA * 2 + 2 * BCHUNK)

__global__ void vocab_all(const float* __restrict__ bias, const int* __restrict__ y) {
    extern __shared__ __align__(16) char smem_raw[];
    __nv_bfloat16* As = (__nv_bfloat16*)smem_raw;
    __nv_bfloat16* Bsm = (__nv_bfloat16*)(smem_raw + 64 * SA * 2);
    __shared__ float s_max[64][2];
    __shared__ float s_sum[64][2];
    __shared__ int s_tgt[64];
    const int tid = threadIdx.x;
    const int t = blockIdx.y;
    const int vbase = blockIdx.x * 128;
    const uint32_t bsm_addr = (uint32_t)__cvta_generic_to_shared(Bsm);
    {
#pragma unroll
        for (int j = 0; j < 2; j++) {
            int seg = tid * 2 + j;
            int n = seg >> 2, part = seg & 3;
            cp16(bsm_addr + (uint32_t)(n * SBW + part * 8) * 2,
                 g_Wvb + (size_t)(vbase + n) * 512 + part * 8);
        }
        asm volatile("cp.async.commit_group;\n");
    }
    if (tid < 64) s_tgt[tid] = y[(t + 1) * 64 + tid];
    {
        const __nv_bfloat16* lg = g_logit_bf + (size_t)t * 64 * 512;
        for (int i = tid; i < 64 * 64; i += 256) {
            int m = i >> 6, c = i & 63;
            *(uint4*)(As + m * SA + c * 8) = *(const uint4*)(lg + m * 512 + c * 8);
        }
    }
    const int warp = tid >> 5, lane = tid & 31;
    const int wm = (warp & 3) * 16, wn = (warp >> 2) * 64, nw = warp >> 2;
    const int g = lane >> 2, t2 = (lane & 3) * 2;
    float acc[8][4];
#pragma unroll
    for (int f = 0; f < 8; f++)
#pragma unroll
        for (int j = 0; j < 4; j++) acc[f][j] = 0.f;
    int buf = 0;
    for (int kc = 0; kc < 512; kc += 32) {
        if (kc + 32 < 512) {
            uint32_t dst = bsm_addr + (buf ^ 1) * BCHUNK;
#pragma unroll
            for (int j = 0; j < 2; j++) {
                int seg = tid * 2 + j;
                int n = seg >> 2, part = seg & 3;
                cp16(dst + (uint32_t)(n * SBW + part * 8) * 2,
                     g_Wvb + (size_t)(vbase + n) * 512 + kc + 32 + part * 8);
            }
            asm volatile("cp.async.commit_group;\n");
            asm volatile("cp.async.wait_group 1;\n");
        } else {
            asm volatile("cp.async.wait_group 0;\n");
        }
        __syncthreads();
        const __nv_bfloat16* Bb = Bsm + buf * (BCHUNK / 2);
#pragma unroll
        for (int ks = 0; ks < 2; ks++) {
            int k = kc + ks * 16;
            uint32_t a0 = *(const uint32_t*)(As + (wm + g) * SA + k + t2);
            uint32_t a1 = *(const uint32_t*)(As + (wm + g + 8) * SA + k + t2);
            uint32_t a2 = *(const uint32_t*)(As + (wm + g) * SA + k + t2 + 8);
            uint32_t a3 = *(const uint32_t*)(As + (wm + g + 8) * SA + k + t2 + 8);
            int ko = ks * 16;
#pragma unroll
            for (int f = 0; f < 8; f++) {
                uint32_t b0 = *(const uint32_t*)(Bb + (wn + f * 8 + g) * SBW + ko + t2);
                uint32_t b1 = *(const uint32_t*)(Bb + (wn + f * 8 + g) * SBW + ko + t2 + 8);
                mma_bf16(acc[f][0], acc[f][1], acc[f][2], acc[f][3], a0, a1, a2, a3, b0, b1);
            }
        }
        __syncthreads();
        buf ^= 1;
    }
    float mx0 = -1e30f, mx1 = -1e30f;
#pragma unroll
    for (int f = 0; f < 8; f++) {
        int colg = vbase + wn + f * 8 + t2;
        float b0f = bias[colg], b1f = bias[colg + 1];
        acc[f][0] += b0f; acc[f][1] += b1f;
        acc[f][2] += b0f; acc[f][3] += b1f;
        mx0 = fmaxf(mx0, fmaxf(acc[f][0], acc[f][1]));
        mx1 = fmaxf(mx1, fmaxf(acc[f][2], acc[f][3]));
    }
    mx0 = fmaxf(mx0, __shfl_xor_sync(0xffffffffu, mx0, 1));
    mx0 = fmaxf(mx0, __shfl_xor_sync(0xffffffffu, mx0, 2));
    mx1 = fmaxf(mx1, __shfl_xor_sync(0xffffffffu, mx1, 1));
    mx1 = fmaxf(mx1, __shfl_xor_sync(0xffffffffu, mx1, 2));
    if ((lane & 3) == 0) {
        s_max[wm + g][nw] = mx0;
        s_max[wm + g + 8][nw] = mx1;
    }
    __syncthreads();
    float M0 = fmaxf(s_max[wm + g][0], s_max[wm + g][1]);
    float M1 = fmaxf(s_max[wm + g + 8][0], s_max[wm + g + 8][1]);
    int tg0 = s_tgt[wm + g], tg1 = s_tgt[wm + g + 8];
    float s0 = 0.f, s1 = 0.f;
#pragma unroll
    for (int f = 0; f < 8; f++) {
        int colg = vbase + wn + f * 8 + t2;
        s0 += expf(acc[f][0] - M0) + expf(acc[f][1] - M0);
        s1 += expf(acc[f][2] - M1) + expf(acc[f][3] - M1);
        if (colg == tg0)     g_tgt[t * 64 + wm + g] = acc[f][0];
        if (colg + 1 == tg0) g_tgt[t * 64 + wm + g] = acc[f][1];
        if (colg == tg1)     g_tgt[t * 64 + wm + g + 8] = acc[f][2];
        if (colg + 1 == tg1) g_tgt[t * 64 + wm + g + 8] = acc[f][3];
    }
    s0 += __shfl_xor_sync(0xffffffffu, s0, 1);
    s0 += __shfl_xor_sync(0xffffffffu, s0, 2);
    s1 += __shfl_xor_sync(0xffffffffu, s1, 1);
    s1 += __shfl_xor_sync(0xffffffffu, s1, 2);
    if ((lane & 3) == 0) {
        s_sum[wm + g][nw] = s0;
        s_sum[wm + g + 8][nw] = s1;
    }
    __syncthreads();
    if (tid < 64) {
        size_t o = ((size_t)t * 250 + blockIdx.x) * 64 + tid;
        g_pmax[o] = fmaxf(s_max[tid][0], s_max[tid][1]);
        g_psum[o] = s_sum[tid][0] + s_sum[tid][1];
    }
}

__global__ void loss_per_t(const int* __restrict__ y) {
    int t = blockIdx.x, tid = threadIdx.x;
    int g = tid >> 6, b = tid & 63;
    __shared__ float smax[8][64];
    __shared__ float ssum[8][64];
    const float* pm = g_pmax + (size_t)t * 250 * 64;
    const float* ps = g_psum + (size_t)t * 250 * 64;
    float mx = -1e30f;
    for (int k = g; k < 250; k += 8) mx = fmaxf(mx, pm[k * 64 + b]);
    smax[g][b] = mx;
    __syncthreads();
    if (g == 0) {
#pragma unroll
        for (int j = 1; j < 8; j++) mx = fmaxf(mx, smax[j][b]);
        smax[0][b] = mx;
    }
    __syncthreads();
    mx = smax[0][b];
    float s = 0.f;
    for (int k = g; k < 250; k += 8) s += ps[k * 64 + b] * expf(pm[k * 64 + b] - mx);
    ssum[g][b] = s;
    __syncthreads();
    if (g == 0) {
#pragma unroll
        for (int j = 1; j < 8; j++) s += ssum[j][b];
        float lp = g_tgt[t * 64 + b] - mx - logf(s);
        ssum[0][b] = (y[(t + 1) * 64 + b] != 0) ? -lp : 0.f;
    }
    __syncthreads();
    if (tid == 0) {
        float a = 0.f;
        for (int i = 0; i < 64; i++) a += ssum[0][i];
        g_losst[t] = a;
    }
}

__global__ void loss_final(float* __restrict__ dout) {
    if (threadIdx.x == 0) {
        float a = 0.f;
        for (int i = 0; i < T; i++) a += g_losst[i];
        dout[0] = a;
    }
}

#define SYM(name, sym) \
    void* name##_v; cudaGetSymbolAddress(&name##_v, sym); float* name = (float*)name##_v;

extern "C" void kernel_launch(void* const* d_in, const int* in_sizes, int n_in,
                              void* d_out, int out_size) {
    const float* ctx        = (const float*)d_in[0];
    const float* ctx_mask   = (const float*)d_in[1];
    const float* txt_ctx    = (const float*)d_in[2];
    const int*   y          = (const int*)d_in[3];
    const float* emb        = (const float*)d_in[4];
    const float* W_ctx2ctx  = (const float*)d_in[5];
    const float* W_hid2ctx  = (const float*)d_in[6];
    const float* w_mlp      = (const float*)d_in[7];
    const float* W_ctx2hid  = (const float*)d_in[8];
    const float* W_dec_init = (const float*)d_in[9];
    const float* W_ih0      = (const float*)d_in[10];
    const float* W_hh0      = (const float*)d_in[11];
    const float* b_ih0      = (const float*)d_in[12];
    const float* b_hh0      = (const float*)d_in[13];
    const float* W_ih1      = (const float*)d_in[14];
    const float* W_hh1      = (const float*)d_in[15];
    const float* b_ih1      = (const float*)d_in[16];
    const float* b_hh1      = (const float*)d_in[17];
    const float* W_hid2out  = (const float*)d_in[18];
    const float* b_hid2out  = (const float*)d_in[19];
    const float* W_out2prob = (const float*)d_in[20];
    const float* b_out2prob = (const float*)d_in[21];

    SYM(pWcombo, g_Wcombo) SYM(pWct, g_Wct) SYM(pWdecT, g_WdecT)
    SYM(pCtxp, g_ctxp) SYM(pXall, g_xall) SYM(pGi0, g_gi0)
    SYM(pHall, g_hall) SYM(pLgall, g_lgall)

    static int smem_set = 0;
    if (!smem_set) {
        cudaFuncSetAttribute(vocab_all, cudaFuncAttributeMaxDynamicSharedMemorySize,
                             VOCAB_SMEM);
        smem_set = 1;
    }
    int dev = 0, nsm = 148;
    cudaGetDevice(&dev);
    cudaDeviceGetAttribute(&nsm, cudaDevAttrMultiProcessorCount, dev);

    dim3 tb(32, 8);
    transpose_k<<<dim3(16, 16), tb>>>(W_dec_init, pWdecT, 512, 512);
    transpose_k<<<dim3(16, 16), tb>>>(W_ctx2hid, pWct, 512, 512);
    convert_bf16<<<16000, 256>>>(W_out2prob);
    gather_kernel<<<T * 64, 512>>>(y, emb);
    init_kernel<<<64, 256>>>(ctx, ctx_mask, txt_ctx);
    gemm_tf32<<<dim3(8, 24), 256>>>(W_ih1, pWct, pWcombo, 512);
    gemm_tf32<<<dim3(8, 64), 256>>>(ctx, W_ctx2ctx, pCtxp, 512);
    gemm_tf32<<<dim3(24, 48), 256>>>(pXall, W_ih0, pGi0, 1536);

    // entire recurrence: one persistent kernel, 6 grid barriers per step
    decoder_loop<<<nsm, 256>>>(ctx, ctx_mask, w_mlp, W_hh0, W_hid2ctx, W_hh1,
                               b_ih0, b_hh0, b_ih1, b_hh1);

    gemm_tf32<<<dim3(8, 48), 256>>>(pHall + 64 * 512, W_hid2out, pLgall, 512);
    logit_combine_all<<<T * 64, 512>>>(b_hid2out);
    vocab_all<<<dim3(250, T), 256, VOCAB_SMEM>>>(b_out2prob, y);
    loss_per_t<<<T, 512>>>(y);
    loss_final<<<1, 32>>>((float*)d_out);
}

// round 15
// speedup vs baseline: 1.5105x; 1.5105x over previous
#include <cuda_runtime.h>
#include <cuda_bf16.h>
#include <math.h>
#include <stdint.h>

#define S 64
#define B 64
#define T 48
#define V 32000
#define NEG (-100000000.0f)

__device__ float g_ctxp[S * B * 512];
__device__ float g_xall[T * B * 512];
__device__ float g_gi0[T * B * 1536];
__device__ float g_Wcombo[1536 * 512];
__device__ float g_Wct[512 * 512];
__device__ float g_WdecT[512 * 512];
__device__ __nv_bfloat16 g_Wvb[(size_t)V * 512];
__device__ float g_hall[(T + 1) * B * 512];
__device__ float g_h1[B * 512];
__device__ float g_z[B * 512];
__device__ float g_ghp[2 * B * 1536];
__device__ float g_qp[2 * B * 512];
__device__ float g_gi1p[2 * B * 1536];
__device__ float g_gh1p[2 * B * 1536];
__device__ float g_lgall[T * B * 512];
__device__ __nv_bfloat16 g_logit_bf[T * B * 512];
__device__ float g_pmax[T * 250 * B];
__device__ float g_psum[T * 250 * B];
__device__ float g_tgt[T * B];
__device__ float g_losst[T];

#define GDC_WAIT() asm volatile("griddepcontrol.wait;" ::: "memory")

__device__ __forceinline__ float tanh_fast(float x) {
    float y;
    asm("tanh.approx.f32 %0, %1;" : "=f"(y) : "f"(x));
    return y;
}

__device__ __forceinline__ uint32_t f2tf(float x) {
    uint32_t r;
    asm("cvt.rna.tf32.f32 %0, %1;" : "=r"(r) : "f"(x));
    return r;
}

__device__ __forceinline__ void mma_tf32(float* c, uint32_t a0, uint32_t a1,
                                         uint32_t a2, uint32_t a3,
                                         uint32_t b0, uint32_t b1) {
    asm volatile(
        "mma.sync.aligned.m16n8k8.row.col.f32.tf32.tf32.f32 "
        "{%0,%1,%2,%3}, {%4,%5,%6,%7}, {%8,%9}, {%0,%1,%2,%3};\n"
        : "+f"(c[0]), "+f"(c[1]), "+f"(c[2]), "+f"(c[3])
        : "r"(a0), "r"(a1), "r"(a2), "r"(a3), "r"(b0), "r"(b1));
}

// ---------------------------------------------------------------------------
// tf32 mma tile: C[64 x 64 tile] = A[rows m0.. x 512] @ W[N x 512]^T over
// K range [k0, k0+KS).  C points at the (possibly partial) output buffer.
// ---------------------------------------------------------------------------
__device__ __forceinline__ void tile_tf32(const float* __restrict__ A,
                                          const float* __restrict__ W,
                                          float* __restrict__ C,
                                          int N, int n0, int m0, int k0, int KS,
                                          uint32_t (*As)[20], uint32_t (*Ws)[20]) {
    const int tid = threadIdx.x;
    const int warp = tid >> 5, lane = tid & 31;
    const int wm = (warp & 3) * 16, wn = (warp >> 2) * 32;
    const int g = lane >> 2, tk = lane & 3;
    const int lr = tid >> 2, lc = (tid & 3) * 4;

    const float* Ap = A + (size_t)(m0 + lr) * 512 + k0 + lc;
    const float* Wp = W + (size_t)(n0 + lr) * 512 + k0 + lc;
    float4 ra = *(const float4*)Ap;
    float4 rw = *(const float4*)Wp;

    float acc[4][4];
#pragma unroll
    for (int f = 0; f < 4; f++)
#pragma unroll
        for (int j = 0; j < 4; j++) acc[f][j] = 0.f;

    for (int rel = 0; rel < KS; rel += 16) {
        As[lr][lc + 0] = f2tf(ra.x); As[lr][lc + 1] = f2tf(ra.y);
        As[lr][lc + 2] = f2tf(ra.z); As[lr][lc + 3] = f2tf(ra.w);
        Ws[lr][lc + 0] = f2tf(rw.x); Ws[lr][lc + 1] = f2tf(rw.y);
        Ws[lr][lc + 2] = f2tf(rw.z); Ws[lr][lc + 3] = f2tf(rw.w);
        __syncthreads();
        if (rel + 16 < KS) {
            ra = *(const float4*)(Ap + rel + 16);
            rw = *(const float4*)(Wp + rel + 16);
        }
#pragma unroll
        for (int ks = 0; ks < 16; ks += 8) {
            uint32_t a0 = As[wm + g][ks + tk];
            uint32_t a1 = As[wm + g + 8][ks + tk];
            uint32_t a2 = As[wm + g][ks + tk + 4];
            uint32_t a3 = As[wm + g + 8][ks + tk + 4];
#pragma unroll
            for (int f = 0; f < 4; f++) {
                uint32_t b0 = Ws[wn + f * 8 + g][ks + tk];
                uint32_t b1 = Ws[wn + f * 8 + g][ks + tk + 4];
                mma_tf32(acc[f], a0, a1, a2, a3, b0, b1);
            }
        }
        __syncthreads();
    }
    const int r0 = m0 + wm + g, r1 = r0 + 8;
#pragma unroll
    for (int f = 0; f < 4; f++) {
        int c = n0 + wn + f * 8 + tk * 2;
        C[(size_t)r0 * N + c]     = acc[f][0];
        C[(size_t)r0 * N + c + 1] = acc[f][1];
        C[(size_t)r1 * N + c]     = acc[f][2];
        C[(size_t)r1 * N + c + 1] = acc[f][3];
    }
}

// prologue GEMM (full K, no PDL)
__global__ void __launch_bounds__(256, 2)
gemm_tf32(const float* __restrict__ A, const float* __restrict__ W,
          float* __restrict__ C, int N) {
    __shared__ uint32_t As[64][20];
    __shared__ uint32_t Ws[64][20];
    tile_tf32(A, W, C, N, blockIdx.x * 64, blockIdx.y * 64, 0, 512, As, Ws);
}

// ---------------- in-loop kernels (PDL: griddepcontrol.wait at entry) ------
__global__ void __launch_bounds__(256, 2)
k_gh0(const float* __restrict__ ht, const float* __restrict__ Whh0) {
    __shared__ uint32_t As[64][20];
    __shared__ uint32_t Ws[64][20];
    GDC_WAIT();
    int nt = blockIdx.x % 24, ks = blockIdx.x / 24;   // grid 48
    tile_tf32(ht, Whh0, g_ghp + (size_t)ks * 98304, 1536, nt * 64, 0,
              ks * 256, 256, As, Ws);
}

__global__ void __launch_bounds__(512)
k_gru0(const float* __restrict__ gi, const float* __restrict__ ht,
       const float* __restrict__ bih, const float* __restrict__ bhh) {
    GDC_WAIT();
    int b = blockIdx.x, h = threadIdx.x;
    size_t base = (size_t)b * 1536 + h;
    float ir = gi[base] + bih[h];
    float iz = gi[base + 512] + bih[512 + h];
    float in_ = gi[base + 1024] + bih[1024 + h];
    float hr = g_ghp[base] + g_ghp[98304 + base] + bhh[h];
    float hz = g_ghp[base + 512] + g_ghp[98304 + base + 512] + bhh[512 + h];
    float hn = g_ghp[base + 1024] + g_ghp[98304 + base + 1024] + bhh[1024 + h];
    float r = 1.f / (1.f + expf(-(ir + hr)));
    float zg = 1.f / (1.f + expf(-(iz + hz)));
    float n = tanhf(in_ + r * hn);
    g_h1[b * 512 + h] = (1.f - zg) * n + zg * ht[b * 512 + h];
}

__global__ void __launch_bounds__(256, 2)
k_q(const float* __restrict__ Whc) {
    __shared__ uint32_t As[64][20];
    __shared__ uint32_t Ws[64][20];
    GDC_WAIT();
    int nt = blockIdx.x % 8, ks = blockIdx.x / 8;     // grid 16
    tile_tf32(g_h1, Whc, g_qp + (size_t)ks * 32768, 512, nt * 64, 0,
              ks * 256, 256, As, Ws);
}

__global__ void __launch_bounds__(256)
k_attn(const float* __restrict__ ctx, const float* __restrict__ mask,
       const float* __restrict__ w_mlp) {
    GDC_WAIT();
    int b = blockIdx.x, tid = threadIdx.x;
    __shared__ float qs[512];
    __shared__ float sc[64];
    for (int i = tid; i < 512; i += 256)
        qs[i] = g_qp[b * 512 + i] + g_qp[32768 + b * 512 + i];
    __syncthreads();
    int warp = tid >> 5, lane = tid & 31;
    for (int s = warp; s < 64; s += 8) {
        float acc = 0.f;
        const float* cp = &g_ctxp[((size_t)s * 64 + b) * 512];
        for (int c = lane; c < 512; c += 32)
            acc += tanh_fast(cp[c] + qs[c]) * w_mlp[c];
#pragma unroll
        for (int o = 16; o > 0; o >>= 1) acc += __shfl_xor_sync(0xffffffffu, acc, o);
        if (lane == 0) sc[s] = (mask[s * 64 + b] > 0.f) ? acc : NEG;
    }
    __syncthreads();
    if (warp == 0) {
        float v0 = sc[lane], v1 = sc[lane + 32];
        float mx = fmaxf(v0, v1);
#pragma unroll
        for (int o = 16; o > 0; o >>= 1) mx = fmaxf(mx, __shfl_xor_sync(0xffffffffu, mx, o));
        float e0 = expf(v0 - mx), e1 = expf(v1 - mx);
        float sm = e0 + e1;
#pragma unroll
        for (int o = 16; o > 0; o >>= 1) sm += __shfl_xor_sync(0xffffffffu, sm, o);
        sc[lane] = e0 / sm;
        sc[lane + 32] = e1 / sm;
    }
    __syncthreads();
    for (int c = tid; c < 512; c += 256) {
        float acc = 0.f;
        for (int s = 0; s < 64; s++)
            acc += sc[s] * ctx[((size_t)s * 64 + b) * 512 + c];
        g_z[b * 512 + c] = acc;
    }
}

__global__ void __launch_bounds__(256, 2)
k_dual(const float* __restrict__ Whh1) {
    __shared__ uint32_t As[64][20];
    __shared__ uint32_t Ws[64][20];
    GDC_WAIT();
    int bx = blockIdx.x;                               // grid 96
    int half = bx / 48, rem = bx % 48;
    int nt = rem % 24, ks = rem / 24;
    if (half == 0)
        tile_tf32(g_z, g_Wcombo, g_gi1p + (size_t)ks * 98304, 1536,
                  nt * 64, 0, ks * 256, 256, As, Ws);
    else
        tile_tf32(g_h1, Whh1, g_gh1p + (size_t)ks * 98304, 1536,
                  nt * 64, 0, ks * 256, 256, As, Ws);
}

__global__ void __launch_bounds__(512)
k_gru1(float* __restrict__ ht1, const float* __restrict__ bih,
       const float* __restrict__ bhh) {
    GDC_WAIT();
    int b = blockIdx.x, h = threadIdx.x;
    size_t base = (size_t)b * 1536 + h;
    float ir = g_gi1p[base] + g_gi1p[98304 + base] + bih[h];
    float iz = g_gi1p[base + 512] + g_gi1p[98304 + base + 512] + bih[512 + h];
    float in_ = g_gi1p[base + 1024] + g_gi1p[98304 + base + 1024] + bih[1024 + h];
    float hr = g_gh1p[base] + g_gh1p[98304 + base] + bhh[h];
    float hz = g_gh1p[base + 512] + g_gh1p[98304 + base + 512] + bhh[512 + h];
    float hn = g_gh1p[base + 1024] + g_gh1p[98304 + base + 1024] + bhh[1024 + h];
    float r = 1.f / (1.f + expf(-(ir + hr)));
    float zg = 1.f / (1.f + expf(-(iz + hz)));
    float n = tanhf(in_ + r * hn);
    ht1[b * 512 + h] = (1.f - zg) * n + zg * g_h1[b * 512 + h];
}

// ---------------- prologue / epilogue ---------------------------------------
__global__ void transpose_k(const float* __restrict__ in, float* __restrict__ out,
                            int R, int Cc) {
    __shared__ float tile[32][33];
    int bx = blockIdx.x * 32, by = blockIdx.y * 32;
    int x = bx + threadIdx.x;
#pragma unroll
    for (int i = 0; i < 32; i += 8)
        tile[threadIdx.y + i][threadIdx.x] = in[(size_t)(by + threadIdx.y + i) * Cc + x];
    __syncthreads();
    int x2 = by + threadIdx.x;
#pragma unroll
    for (int i = 0; i < 32; i += 8)
        out[(size_t)(bx + threadIdx.y + i) * R + x2] = tile[threadIdx.x][threadIdx.y + i];
}

__global__ void convert_bf16(const float* __restrict__ w) {
    size_t i = ((size_t)blockIdx.x * blockDim.x + threadIdx.x) * 4;
#pragma unroll
    for (int j = 0; j < 4; j++) g_Wvb[i + j] = __float2bfloat16(w[i + j]);
}

__global__ void gather_kernel(const int* __restrict__ y, const float* __restrict__ emb) {
    int blk = blockIdx.x;
    int t = blk >> 6, b = blk & 63;
    int id = y[t * 64 + b];
    g_xall[(size_t)blk * 512 + threadIdx.x] = emb[(size_t)id * 512 + threadIdx.x];
}

__global__ void init_kernel(const float* __restrict__ ctx, const float* __restrict__ mask,
                            const float* __restrict__ txt) {
    int b = blockIdx.x, tid = threadIdx.x;
    __shared__ float mixed[512];
    __shared__ float denom;
    float msum[2];
#pragma unroll
    for (int j = 0; j < 2; j++) {
        int c = tid + 256 * j;
        float m = 0.f;
        for (int s = 0; s < S; s++) m += ctx[((size_t)s * 64 + b) * 512 + c];
        msum[j] = m;
    }
    if (tid == 0) {
        float d = 0.f;
        for (int s = 0; s < S; s++) d += mask[s * 64 + b];
        denom = d;
    }
    __syncthreads();
#pragma unroll
    for (int j = 0; j < 2; j++) {
        int c = tid + 256 * j;
        mixed[c] = 0.5f * (msum[j] / denom) + 0.5f * txt[b * 512 + c];
    }
    __syncthreads();
    for (int h = tid; h < 512; h += 256) {
        float a = 0.f;
        for (int c = 0; c < 512; c++) a += mixed[c] * g_WdecT[c * 512 + h];
        g_hall[b * 512 + h] = tanhf(a);
    }
}

__global__ void logit_combine_all(const float* __restrict__ bias) {
    int row = blockIdx.x, e = threadIdx.x;
    float v = g_lgall[(size_t)row * 512 + e];
    g_logit_bf[(size_t)row * 512 + e] = __float2bfloat16(tanhf(v + bias[e]));
}

__device__ __forceinline__ void mma_bf16(float& c0, float& c1, float& c2, float& c3,
                                         uint32_t a0, uint32_t a1, uint32_t a2, uint32_t a3,
                                         uint32_t b0, uint32_t b1) {
    asm volatile(
        "mma.sync.aligned.m16n8k16.row.col.f32.bf16.bf16.f32 "
        "{%0,%1,%2,%3}, {%4,%5,%6,%7}, {%8,%9}, {%0,%1,%2,%3};\n"
        : "+f"(c0), "+f"(c1), "+f"(c2), "+f"(c3)
        : "r"(a0), "r"(a1), "r"(a2), "r"(a3), "r"(b0), "r"(b1));
}

__device__ __forceinline__ void cp16(uint32_t dst, const void* src) {
    asm volatile("cp.async.cg.shared.global [%0], [%1], 16;\n" :: "r"(dst), "l"(src));
}

#define SA 528
#define SBW 40
#define BCHUNK (128 * SBW * 2)
#define VOCAB_SMEM (64 * SA * 2 + 2 * BCHUNK)

__global__ void vocab_all(const float* __restrict__ bias, const int* __restrict__ y) {
    extern __shared__ __align__(16) char smem_raw[];
    __nv_bfloat16* As = (__nv_bfloat16*)smem_raw;
    __nv_bfloat16* Bsm = (__nv_bfloat16*)(smem_raw + 64 * SA * 2);
    __shared__ float s_max[64][2];
    __shared__ float s_sum[64][2];
    __shared__ int s_tgt[64];
    const int tid = threadIdx.x;
    const int t = blockIdx.y;
    const int vbase = blockIdx.x * 128;
    const uint32_t bsm_addr = (uint32_t)__cvta_generic_to_shared(Bsm);
    {
#pragma unroll
        for (int j = 0; j < 2; j++) {
            int seg = tid * 2 + j;
            int n = seg >> 2, part = seg & 3;
            cp16(bsm_addr + (uint32_t)(n * SBW + part * 8) * 2,
                 g_Wvb + (size_t)(vbase + n) * 512 + part * 8);
        }
        asm volatile("cp.async.commit_group;\n");
    }
    if (tid < 64) s_tgt[tid] = y[(t + 1) * 64 + tid];
    {
        const __nv_bfloat16* lg = g_logit_bf + (size_t)t * 64 * 512;
        for (int i = tid; i < 64 * 64; i += 256) {
            int m = i >> 6, c = i & 63;
            *(uint4*)(As + m * SA + c * 8) = *(const uint4*)(lg + m * 512 + c * 8);
        }
    }
    const int warp = tid >> 5, lane = tid & 31;
    const int wm = (warp & 3) * 16, wn = (warp >> 2) * 64, nw = warp >> 2;
    const int g = lane >> 2, t2 = (lane & 3) * 2;
    float acc[8][4];
#pragma unroll
    for (int f = 0; f < 8; f++)
#pragma unroll
        for (int j = 0; j < 4; j++) acc[f][j] = 0.f;
    int buf = 0;
    for (int kc = 0; kc < 512; kc += 32) {
        if (kc + 32 < 512) {
            uint32_t dst = bsm_addr + (buf ^ 1) * BCHUNK;
#pragma unroll
            for (int j = 0; j < 2; j++) {
                int seg = tid * 2 + j;
                int n = seg >> 2, part = seg & 3;
                cp16(dst + (uint32_t)(n * SBW + part * 8) * 2,
                     g_Wvb + (size_t)(vbase + n) * 512 + kc + 32 + part * 8);
            }
            asm volatile("cp.async.commit_group;\n");
            asm volatile("cp.async.wait_group 1;\n");
        } else {
            asm volatile("cp.async.wait_group 0;\n");
        }
        __syncthreads();
        const __nv_bfloat16* Bb = Bsm + buf * (BCHUNK / 2);
#pragma unroll
        for (int ks = 0; ks < 2; ks++) {
            int k = kc + ks * 16;
            uint32_t a0 = *(const uint32_t*)(As + (wm + g) * SA + k + t2);
            uint32_t a1 = *(const uint32_t*)(As + (wm + g + 8) * SA + k + t2);
            uint32_t a2 = *(const uint32_t*)(As + (wm + g) * SA + k + t2 + 8);
            uint32_t a3 = *(const uint32_t*)(As + (wm + g + 8) * SA + k + t2 + 8);
            int ko = ks * 16;
#pragma unroll
            for (int f = 0; f < 8; f++) {
                uint32_t b0 = *(const uint32_t*)(Bb + (wn + f * 8 + g) * SBW + ko + t2);
                uint32_t b1 = *(const uint32_t*)(Bb + (wn + f * 8 + g) * SBW + ko + t2 + 8);
                mma_bf16(acc[f][0], acc[f][1], acc[f][2], acc[f][3], a0, a1, a2, a3, b0, b1);
            }
        }
        __syncthreads();
        buf ^= 1;
    }
    float mx0 = -1e30f, mx1 = -1e30f;
#pragma unroll
    for (int f = 0; f < 8; f++) {
        int colg = vbase + wn + f * 8 + t2;
        float b0f = bias[colg], b1f = bias[colg + 1];
        acc[f][0] += b0f; acc[f][1] += b1f;
        acc[f][2] += b0f; acc[f][3] += b1f;
        mx0 = fmaxf(mx0, fmaxf(acc[f][0], acc[f][1]));
        mx1 = fmaxf(mx1, fmaxf(acc[f][2], acc[f][3]));
    }
    mx0 = fmaxf(mx0, __shfl_xor_sync(0xffffffffu, mx0, 1));
    mx0 = fmaxf(mx0, __shfl_xor_sync(0xffffffffu, mx0, 2));
    mx1 = fmaxf(mx1, __shfl_xor_sync(0xffffffffu, mx1, 1));
    mx1 = fmaxf(mx1, __shfl_xor_sync(0xffffffffu, mx1, 2));
    if ((lane & 3) == 0) {
        s_max[wm + g][nw] = mx0;
        s_max[wm + g + 8][nw] = mx1;
    }
    __syncthreads();
    float M0 = fmaxf(s_max[wm + g][0], s_max[wm + g][1]);
    float M1 = fmaxf(s_max[wm + g + 8][0], s_max[wm + g + 8][1]);
    int tg0 = s_tgt[wm + g], tg1 = s_tgt[wm + g + 8];
    float s0 = 0.f, s1 = 0.f;
#pragma unroll
    for (int f = 0; f < 8; f++) {
        int colg = vbase + wn + f * 8 + t2;
        s0 += expf(acc[f][0] - M0) + expf(acc[f][1] - M0);
        s1 += expf(acc[f][2] - M1) + expf(acc[f][3] - M1);
        if (colg == tg0)     g_tgt[t * 64 + wm + g] = acc[f][0];
        if (colg + 1 == tg0) g_tgt[t * 64 + wm + g] = acc[f][1];
        if (colg == tg1)     g_tgt[t * 64 + wm + g + 8] = acc[f][2];
        if (colg + 1 == tg1) g_tgt[t * 64 + wm + g + 8] = acc[f][3];
    }
    s0 += __shfl_xor_sync(0xffffffffu, s0, 1);
    s0 += __shfl_xor_sync(0xffffffffu, s0, 2);
    s1 += __shfl_xor_sync(0xffffffffu, s1, 1);
    s1 += __shfl_xor_sync(0xffffffffu, s1, 2);
    if ((lane & 3) == 0) {
        s_sum[wm + g][nw] = s0;
        s_sum[wm + g + 8][nw] = s1;
    }
    __syncthreads();
    if (tid < 64) {
        size_t o = ((size_t)t * 250 + blockIdx.x) * 64 + tid;
        g_pmax[o] = fmaxf(s_max[tid][0], s_max[tid][1]);
        g_psum[o] = s_sum[tid][0] + s_sum[tid][1];
    }
}

__global__ void loss_per_t(const int* __restrict__ y) {
    int t = blockIdx.x, tid = threadIdx.x;
    int g = tid >> 6, b = tid & 63;
    __shared__ float smax[8][64];
    __shared__ float ssum[8][64];
    const float* pm = g_pmax + (size_t)t * 250 * 64;
    const float* ps = g_psum + (size_t)t * 250 * 64;
    float mx = -1e30f;
    for (int k = g; k < 250; k += 8) mx = fmaxf(mx, pm[k * 64 + b]);
    smax[g][b] = mx;
    __syncthreads();
    if (g == 0) {
#pragma unroll
        for (int j = 1; j < 8; j++) mx = fmaxf(mx, smax[j][b]);
        smax[0][b] = mx;
    }
    __syncthreads();
    mx = smax[0][b];
    float s = 0.f;
    for (int k = g; k < 250; k += 8) s += ps[k * 64 + b] * expf(pm[k * 64 + b] - mx);
    ssum[g][b] = s;
    __syncthreads();
    if (g == 0) {
#pragma unroll
        for (int j = 1; j < 8; j++) s += ssum[j][b];
        float lp = g_tgt[t * 64 + b] - mx - logf(s);
        ssum[0][b] = (y[(t + 1) * 64 + b] != 0) ? -lp : 0.f;
    }
    __syncthreads();
    if (tid == 0) {
        float a = 0.f;
        for (int i = 0; i < 64; i++) a += ssum[0][i];
        g_losst[t] = a;
    }
}

__global__ void loss_final(float* __restrict__ dout) {
    if (threadIdx.x == 0) {
        float a = 0.f;
        for (int i = 0; i < T; i++) a += g_losst[i];
        dout[0] = a;
    }
}

#define SYM(name, sym) \
    void* name##_v; cudaGetSymbolAddress(&name##_v, sym); float* name = (float*)name##_v;

// PDL launch helper: programmatic stream serialization on the legacy stream.
#define EX_PDL(grid, block, fn, ...) do {                                     \
    cudaLaunchAttribute _at;                                                  \
    _at.id = cudaLaunchAttributeProgrammaticStreamSerialization;              \
    _at.val.programmaticStreamSerializationAllowed = 1;                       \
    cudaLaunchConfig_t _cfg;                                                  \
    _cfg.gridDim = grid; _cfg.blockDim = block;                               \
    _cfg.dynamicSmemBytes = 0; _cfg.stream = 0;                               \
    _cfg.attrs = &_at; _cfg.numAttrs = 1;                                     \
    cudaLaunchKernelEx(&_cfg, fn, __VA_ARGS__);                               \
} while (0)

extern "C" void kernel_launch(void* const* d_in, const int* in_sizes, int n_in,
                              void* d_out, int out_size) {
    const float* ctx        = (const float*)d_in[0];
    const float* ctx_mask   = (const float*)d_in[1];
    const float* txt_ctx    = (const float*)d_in[2];
    const int*   y          = (const int*)d_in[3];
    const float* emb        = (const float*)d_in[4];
    const float* W_ctx2ctx  = (const float*)d_in[5];
    const float* W_hid2ctx  = (const float*)d_in[6];
    const float* w_mlp      = (const float*)d_in[7];
    const float* W_ctx2hid  = (const float*)d_in[8];
    const float* W_dec_init = (const float*)d_in[9];
    const float* W_ih0      = (const float*)d_in[10];
    const float* W_hh0      = (const float*)d_in[11];
    const float* b_ih0      = (const float*)d_in[12];
    const float* b_hh0      = (const float*)d_in[13];
    const float* W_ih1      = (const float*)d_in[14];
    const float* W_hh1      = (const float*)d_in[15];
    const float* b_ih1      = (const float*)d_in[16];
    const float* b_hh1      = (const float*)d_in[17];
    const float* W_hid2out  = (const float*)d_in[18];
    const float* b_hid2out  = (const float*)d_in[19];
    const float* W_out2prob = (const float*)d_in[20];
    const float* b_out2prob = (const float*)d_in[21];

    SYM(pWcombo, g_Wcombo) SYM(pWct, g_Wct) SYM(pWdecT, g_WdecT)
    SYM(pCtxp, g_ctxp) SYM(pXall, g_xall) SYM(pGi0, g_gi0)
    SYM(pHall, g_hall) SYM(pLgall, g_lgall)

    static int smem_set = 0;
    if (!smem_set) {
        cudaFuncSetAttribute(vocab_all, cudaFuncAttributeMaxDynamicSharedMemorySize,
                             VOCAB_SMEM);
        smem_set = 1;
    }

    dim3 tb(32, 8);
    transpose_k<<<dim3(16, 16), tb>>>(W_dec_init, pWdecT, 512, 512);
    transpose_k<<<dim3(16, 16), tb>>>(W_ctx2hid, pWct, 512, 512);
    convert_bf16<<<16000, 256>>>(W_out2prob);
    gather_kernel<<<T * 64, 512>>>(y, emb);
    init_kernel<<<64, 256>>>(ctx, ctx_mask, txt_ctx);
    gemm_tf32<<<dim3(8, 24), 256>>>(W_ih1, pWct, pWcombo, 512);
    gemm_tf32<<<dim3(8, 64), 256>>>(ctx, W_ctx2ctx, pCtxp, 512);
    gemm_tf32<<<dim3(24, 48), 256>>>(pXall, W_ih0, pGi0, 1536);

    for (int t = 0; t < T; t++) {
        const float* ht = pHall + (size_t)t * 64 * 512;
        float* ht1 = pHall + (size_t)(t + 1) * 64 * 512;
        const float* gi = pGi0 + (size_t)t * 64 * 1536;
        EX_PDL(dim3(48), dim3(256), k_gh0, ht, W_hh0);
        EX_PDL(dim3(64), dim3(512), k_gru0, gi, ht, b_ih0, b_hh0);
        EX_PDL(dim3(16), dim3(256), k_q, W_hid2ctx);
        EX_PDL(dim3(64), dim3(256), k_attn, ctx, ctx_mask, w_mlp);
        EX_PDL(dim3(96), dim3(256), k_dual, W_hh1);
        EX_PDL(dim3(64), dim3(512), k_gru1, ht1, b_ih1, b_hh1);
    }

    gemm_tf32<<<dim3(8, 48), 256>>>(pHall + 64 * 512, W_hid2out, pLgall, 512);
    logit_combine_all<<<T * 64, 512>>>(b_hid2out);
    vocab_all<<<dim3(250, T), 256, VOCAB_SMEM>>>(b_out2prob, y);
    loss_per_t<<<T, 512>>>(y);
    loss_final<<<1, 32>>>((float*)d_out);
}